// round 1
// baseline (speedup 1.0000x reference)
#include <cuda_runtime.h>
#include <cstdint>

#define M_DIM 16384
#define N_DIM 65536
#define NNZ   4194304
#define BATCH 16

// Scratch (allocation-free rule: __device__ globals)
__device__ float g_t1[M_DIM * BATCH];     // [M,16] -> then reused as r
__device__ float g_zuT[N_DIM * BATCH];    // [N,16]
__device__ float g_t2T[N_DIM * BATCH];    // [N,16]
__device__ float g_norm[BATCH];

// K0: zu_T = (z*u) transposed to [N,16]; zero t1, t2T, norms
__global__ void k_init(const float* __restrict__ z, const float* __restrict__ u) {
    int idx = blockIdx.x * blockDim.x + threadIdx.x;   // idx = b*N + n (coalesced reads)
    if (idx < N_DIM * BATCH) {
        int b = idx >> 16;            // N = 65536
        int n = idx & (N_DIM - 1);
        g_zuT[n * BATCH + b] = z[idx] * u[idx];
        g_t2T[idx] = 0.0f;
        if (idx < M_DIM * BATCH) g_t1[idx] = 0.0f;
        if (idx < BATCH) g_norm[idx] = 0.0f;
    }
}

// K1: t1[row,b] += val * zu_T[col,b]   (16 lanes per nnz)
__global__ void k_spmm1(const float* __restrict__ vals,
                        const int* __restrict__ rows,
                        const int* __restrict__ cols) {
    int tid = blockIdx.x * blockDim.x + threadIdx.x;   // NNZ*16 = 2^26
    int i = tid >> 4;
    int b = tid & 15;
    if (i < NNZ) {
        float v  = __ldg(&vals[i]);
        int   r  = __ldg(&rows[i]);
        int   c  = __ldg(&cols[i]);
        atomicAdd(&g_t1[r * BATCH + b], v * g_zuT[c * BATCH + b]);
    }
}

// K2: r = y - t1 (in place, in [M,16] layout)
__global__ void k_residual(const float* __restrict__ y) {
    int idx = blockIdx.x * blockDim.x + threadIdx.x;   // idx = b*M + m (coalesced y read)
    if (idx < M_DIM * BATCH) {
        int b = idx >> 14;            // M = 16384
        int m = idx & (M_DIM - 1);
        int t = m * BATCH + b;
        g_t1[t] = y[idx] - g_t1[t];
    }
}

// K3: t2_T[col,b] += val * r[row,b]
__global__ void k_spmm2(const float* __restrict__ vals,
                        const int* __restrict__ rows,
                        const int* __restrict__ cols) {
    int tid = blockIdx.x * blockDim.x + threadIdx.x;
    int i = tid >> 4;
    int b = tid & 15;
    if (i < NNZ) {
        float v  = __ldg(&vals[i]);
        int   r  = __ldg(&rows[i]);
        int   c  = __ldg(&cols[i]);
        atomicAdd(&g_t2T[c * BATCH + b], v * g_t1[r * BATCH + b]);
    }
}

// K4: per-batch sum of squares of v = u * t2
__global__ void k_norm(const float* __restrict__ u) {
    int b = blockIdx.y;
    float acc = 0.0f;
    for (int n = blockIdx.x * blockDim.x + threadIdx.x; n < N_DIM;
         n += gridDim.x * blockDim.x) {
        float v = u[b * N_DIM + n] * g_t2T[n * BATCH + b];
        acc += v * v;
    }
    // warp reduce
    #pragma unroll
    for (int off = 16; off > 0; off >>= 1)
        acc += __shfl_down_sync(0xFFFFFFFFu, acc, off);
    __shared__ float warp_sums[8];
    int lane = threadIdx.x & 31, wid = threadIdx.x >> 5;
    if (lane == 0) warp_sums[wid] = acc;
    __syncthreads();
    if (wid == 0) {
        acc = (lane < (blockDim.x >> 5)) ? warp_sums[lane] : 0.0f;
        #pragma unroll
        for (int off = 4; off > 0; off >>= 1)
            acc += __shfl_down_sync(0xFFFFFFFFu, acc, off);
        if (lane == 0) atomicAdd(&g_norm[b], acc);
    }
}

// K5: out = z - eta * v / max(1, ||v||)
__global__ void k_final(const float* __restrict__ z,
                        const float* __restrict__ u,
                        const float* __restrict__ eta,
                        float* __restrict__ out) {
    int idx = blockIdx.x * blockDim.x + threadIdx.x;   // b*N + n
    if (idx < N_DIM * BATCH) {
        int b = idx >> 16;
        int n = idx & (N_DIM - 1);
        float nrm = sqrtf(g_norm[b]);
        float scale = 1.0f / fmaxf(1.0f, nrm);
        float v = u[idx] * g_t2T[n * BATCH + b];
        out[idx] = z[idx] - eta[0] * v * scale;
    }
}

extern "C" void kernel_launch(void* const* d_in, const int* in_sizes, int n_in,
                              void* d_out, int out_size) {
    const float* z      = (const float*)d_in[0];
    const float* u      = (const float*)d_in[1];
    const float* y      = (const float*)d_in[2];
    const float* A_vals = (const float*)d_in[3];
    const int*   A_rows = (const int*)d_in[4];
    const int*   A_cols = (const int*)d_in[5];
    const float* eta    = (const float*)d_in[6];
    float* out = (float*)d_out;

    const int T = 256;
    k_init<<<(N_DIM * BATCH + T - 1) / T, T>>>(z, u);
    k_spmm1<<<(NNZ * BATCH) / T, T>>>(A_vals, A_rows, A_cols);
    k_residual<<<(M_DIM * BATCH + T - 1) / T, T>>>(y);
    k_spmm2<<<(NNZ * BATCH) / T, T>>>(A_vals, A_rows, A_cols);
    dim3 ng(64, BATCH, 1);
    k_norm<<<ng, T>>>(u);
    k_final<<<(N_DIM * BATCH + T - 1) / T, T>>>(z, u, eta, out);
}

// round 2
// speedup vs baseline: 2.0852x; 2.0852x over previous
#include <cuda_runtime.h>
#include <cstdint>

#define M_DIM 16384
#define N_DIM 65536
#define NNZ   4194304
#define BATCH 16

// Scratch (allocation-free rule: __device__ globals). 16B-aligned for v4 ops.
__device__ __align__(16) float g_t1[M_DIM * BATCH];     // [M,16] -> then reused as r
__device__ __align__(16) float g_zuT[N_DIM * BATCH];    // [N,16]
__device__ __align__(16) float g_t2T[N_DIM * BATCH];    // [N,16]
__device__ float g_norm[BATCH];

__device__ __forceinline__ void red_add_v4(float* addr, float4 v) {
    asm volatile("red.global.add.v4.f32 [%0], {%1, %2, %3, %4};"
                 :: "l"(addr), "f"(v.x), "f"(v.y), "f"(v.z), "f"(v.w)
                 : "memory");
}

// K0: zu_T = (z*u) transposed to [N,16]; zero t1, t2T, norms
__global__ void k_init(const float* __restrict__ z, const float* __restrict__ u) {
    int idx = blockIdx.x * blockDim.x + threadIdx.x;   // idx = b*N + n (coalesced reads)
    if (idx < N_DIM * BATCH) {
        int b = idx >> 16;            // N = 65536
        int n = idx & (N_DIM - 1);
        g_zuT[n * BATCH + b] = z[idx] * u[idx];
        g_t2T[idx] = 0.0f;
        if (idx < M_DIM * BATCH) g_t1[idx] = 0.0f;
        if (idx < BATCH) g_norm[idx] = 0.0f;
    }
}

// K1: t1[row, b4:b4+4] += val * zu_T[col, b4:b4+4]   (4 lanes per nnz, v4 reds)
__global__ void k_spmm1(const float* __restrict__ vals,
                        const int* __restrict__ rows,
                        const int* __restrict__ cols) {
    int tid = blockIdx.x * blockDim.x + threadIdx.x;   // NNZ*4 = 2^24
    int i  = tid >> 2;
    int b4 = (tid & 3) << 2;
    if (i < NNZ) {
        float v = __ldg(&vals[i]);
        int   r = __ldg(&rows[i]);
        int   c = __ldg(&cols[i]);
        float4 x = *reinterpret_cast<const float4*>(&g_zuT[c * BATCH + b4]);
        float4 p = make_float4(v * x.x, v * x.y, v * x.z, v * x.w);
        red_add_v4(&g_t1[r * BATCH + b4], p);
    }
}

// K2: r = y - t1 (in place, [M,16] layout)
__global__ void k_residual(const float* __restrict__ y) {
    int idx = blockIdx.x * blockDim.x + threadIdx.x;   // idx = b*M + m (coalesced y read)
    if (idx < M_DIM * BATCH) {
        int b = idx >> 14;            // M = 16384
        int m = idx & (M_DIM - 1);
        int t = m * BATCH + b;
        g_t1[t] = y[idx] - g_t1[t];
    }
}

// K3: t2_T[col, b4:b4+4] += val * r[row, b4:b4+4]
__global__ void k_spmm2(const float* __restrict__ vals,
                        const int* __restrict__ rows,
                        const int* __restrict__ cols) {
    int tid = blockIdx.x * blockDim.x + threadIdx.x;
    int i  = tid >> 2;
    int b4 = (tid & 3) << 2;
    if (i < NNZ) {
        float v = __ldg(&vals[i]);
        int   r = __ldg(&rows[i]);
        int   c = __ldg(&cols[i]);
        float4 x = *reinterpret_cast<const float4*>(&g_t1[r * BATCH + b4]);
        float4 p = make_float4(v * x.x, v * x.y, v * x.z, v * x.w);
        red_add_v4(&g_t2T[c * BATCH + b4], p);
    }
}

// K4: per-batch sum of squares of v = u * t2
__global__ void k_norm(const float* __restrict__ u) {
    int b = blockIdx.y;
    float acc = 0.0f;
    for (int n = blockIdx.x * blockDim.x + threadIdx.x; n < N_DIM;
         n += gridDim.x * blockDim.x) {
        float v = u[b * N_DIM + n] * g_t2T[n * BATCH + b];
        acc += v * v;
    }
    #pragma unroll
    for (int off = 16; off > 0; off >>= 1)
        acc += __shfl_down_sync(0xFFFFFFFFu, acc, off);
    __shared__ float warp_sums[8];
    int lane = threadIdx.x & 31, wid = threadIdx.x >> 5;
    if (lane == 0) warp_sums[wid] = acc;
    __syncthreads();
    if (wid == 0) {
        acc = (lane < (blockDim.x >> 5)) ? warp_sums[lane] : 0.0f;
        #pragma unroll
        for (int off = 4; off > 0; off >>= 1)
            acc += __shfl_down_sync(0xFFFFFFFFu, acc, off);
        if (lane == 0) atomicAdd(&g_norm[b], acc);
    }
}

// K5: out = z - eta * v / max(1, ||v||)
__global__ void k_final(const float* __restrict__ z,
                        const float* __restrict__ u,
                        const float* __restrict__ eta,
                        float* __restrict__ out) {
    int idx = blockIdx.x * blockDim.x + threadIdx.x;   // b*N + n
    if (idx < N_DIM * BATCH) {
        int b = idx >> 16;
        int n = idx & (N_DIM - 1);
        float nrm = sqrtf(g_norm[b]);
        float scale = 1.0f / fmaxf(1.0f, nrm);
        float v = u[idx] * g_t2T[n * BATCH + b];
        out[idx] = z[idx] - eta[0] * v * scale;
    }
}

extern "C" void kernel_launch(void* const* d_in, const int* in_sizes, int n_in,
                              void* d_out, int out_size) {
    const float* z      = (const float*)d_in[0];
    const float* u      = (const float*)d_in[1];
    const float* y      = (const float*)d_in[2];
    const float* A_vals = (const float*)d_in[3];
    const int*   A_rows = (const int*)d_in[4];
    const int*   A_cols = (const int*)d_in[5];
    const float* eta    = (const float*)d_in[6];
    float* out = (float*)d_out;

    const int T = 256;
    k_init<<<(N_DIM * BATCH + T - 1) / T, T>>>(z, u);
    k_spmm1<<<(NNZ * 4) / T, T>>>(A_vals, A_rows, A_cols);
    k_residual<<<(M_DIM * BATCH + T - 1) / T, T>>>(y);
    k_spmm2<<<(NNZ * 4) / T, T>>>(A_vals, A_rows, A_cols);
    dim3 ng(64, BATCH, 1);
    k_norm<<<ng, T>>>(u);
    k_final<<<(N_DIM * BATCH + T - 1) / T, T>>>(z, u, eta, out);
}